// round 2
// baseline (speedup 1.0000x reference)
#include <cuda_runtime.h>
#include <cstdint>

#define Bz 8
#define Cc 512
#define Nn 1024

// ---------------- device scratch (no allocations allowed) --------------------
__device__ float g_yf[Bz*Cc*Nn];            // conv output [B,C,N]
__device__ float g_yn[Bz*Cc*Nn];            // layernorm output [B,C,N]
__device__ float g_q [Bz*Nn*Cc];            // q [B,N,C]
__device__ float g_kv[Bz*Nn*2*Cc];          // kv [B,N,2C] (k | v)
__device__ float g_o [Bz*Nn*Cc];            // attn out [B,N,C]
__device__ float g_attn[(size_t)64*1024*1024]; // attn/coeff [64 z][1024 n][1024 m]

// ---------------- kernel 1: fused multi-scale depthwise conv -----------------
__global__ void conv_kernel(const float* __restrict__ y,
                            const float* __restrict__ w3, const float* __restrict__ b3,
                            const float* __restrict__ w5, const float* __restrict__ b5,
                            const float* __restrict__ w7, const float* __restrict__ b7)
{
    int bc = blockIdx.x;            // b*512 + c
    int c  = bc & (Cc-1);
    int t  = threadIdx.x;

    __shared__ float tile[38][38];
    __shared__ float wsum[49];
    __shared__ float bias;

    if (t < 49) {
        int dy = t / 7, dx = t % 7;
        float w = w7[c*49 + t];
        if (dy >= 1 && dy <= 5 && dx >= 1 && dx <= 5) w += w5[c*25 + (dy-1)*5 + (dx-1)];
        if (dy >= 2 && dy <= 4 && dx >= 2 && dx <= 4) w += w3[c*9  + (dy-2)*3 + (dx-2)];
        wsum[t] = w;
    }
    if (t == 64) bias = b3[c] + b5[c] + b7[c];

    const float* yp = y + (size_t)bc * Nn;
    for (int i = t; i < 38*38; i += 256) {
        int r  = i / 38 - 3;
        int cl = i % 38 - 3;
        float v = 0.f;
        if (r >= 0 && r < 32 && cl >= 0 && cl < 32) v = yp[r*32 + cl];
        tile[i/38][i%38] = v;
    }
    __syncthreads();

    float* op = g_yf + (size_t)bc * Nn;
    for (int i = t; i < 1024; i += 256) {
        int r = i >> 5, cl = i & 31;
        float acc = bias;
        #pragma unroll
        for (int dy = 0; dy < 7; dy++)
            #pragma unroll
            for (int dx = 0; dx < 7; dx++)
                acc += wsum[dy*7+dx] * tile[r+dy][cl+dx];
        op[i] = acc;
    }
}

// ---------------- kernel 2: layernorm over C per (b,n), layout [B,C,N] -------
__global__ void ln_kernel(const float* __restrict__ lnw, const float* __restrict__ lnb)
{
    int b    = blockIdx.x >> 5;
    int n0   = (blockIdx.x & 31) * 32;
    int lane = threadIdx.x & 31;
    int g    = threadIdx.x >> 5;            // 0..7
    int n    = n0 + lane;

    const float* base = g_yf + (size_t)b*Cc*Nn + n;
    float s = 0.f, s2 = 0.f;
    for (int c = g; c < Cc; c += 8) {
        float v = base[(size_t)c*Nn];
        s += v; s2 += v*v;
    }
    __shared__ float sh[2][8][32];
    sh[0][g][lane] = s; sh[1][g][lane] = s2;
    __syncthreads();
    if (g == 0) {
        float a = 0.f, a2 = 0.f;
        #pragma unroll
        for (int i = 0; i < 8; i++) { a += sh[0][i][lane]; a2 += sh[1][i][lane]; }
        float mu  = a * (1.f/512.f);
        float var = a2 * (1.f/512.f) - mu*mu;
        sh[0][0][lane] = mu;
        sh[1][0][lane] = rsqrtf(var + 1e-5f);
    }
    __syncthreads();
    float mu = sh[0][0][lane], rs = sh[1][0][lane];
    float* ob = g_yn + (size_t)b*Cc*Nn + n;
    for (int c = g; c < Cc; c += 8) {
        float v = base[(size_t)c*Nn];
        ob[(size_t)c*Nn] = (v - mu) * rs * lnw[c] + lnb[c];
    }
}

// ------- kernels 3/4: OUT[b,n,co] = sum_ci W[co,ci] * X[b,ci,n] ---------------
__global__ void gemm_xw_kernel(const float* __restrict__ W, const float* __restrict__ X,
                               float* __restrict__ OUT, int CO)
{
    __shared__ float Ps[16][68];   // [ci][n]
    __shared__ float Qs[16][68];   // [ci][co]
    int co0 = blockIdx.x * 64, n0 = blockIdx.y * 64, b = blockIdx.z;
    int t = threadIdx.x;
    int tq = t & 15, tp = t >> 4;

    float acc[4][4] = {};
    const float* Xb = X + (size_t)b*Cc*Nn;
    for (int ci0 = 0; ci0 < Cc; ci0 += 16) {
        {   // X tile direct
            int r  = t >> 4;
            int q4 = (t & 15) * 4;
            float4 v = *(const float4*)&Xb[(size_t)(ci0 + r)*Nn + n0 + q4];
            *(float4*)&Ps[r][q4] = v;
        }
        {   // W tile transposed
            int r  = t >> 2;
            int k4 = (t & 3) * 4;
            float4 v = *(const float4*)&W[(size_t)(co0 + r)*Cc + ci0 + k4];
            Qs[k4+0][r] = v.x; Qs[k4+1][r] = v.y; Qs[k4+2][r] = v.z; Qs[k4+3][r] = v.w;
        }
        __syncthreads();
        #pragma unroll
        for (int kk = 0; kk < 16; kk++) {
            float4 pv = *(const float4*)&Ps[kk][tp*4];
            float4 qv = *(const float4*)&Qs[kk][tq*4];
            float pa[4] = {pv.x, pv.y, pv.z, pv.w};
            float qa[4] = {qv.x, qv.y, qv.z, qv.w};
            #pragma unroll
            for (int i = 0; i < 4; i++)
                #pragma unroll
                for (int j = 0; j < 4; j++) acc[i][j] += pa[i]*qa[j];
        }
        __syncthreads();
    }
    #pragma unroll
    for (int i = 0; i < 4; i++) {
        float4 o = make_float4(acc[i][0], acc[i][1], acc[i][2], acc[i][3]);
        *(float4*)&OUT[((size_t)b*Nn + n0 + tp*4 + i)*CO + co0 + tq*4] = o;
    }
}

// ---------------- kernel 5: attn[z,n,m] = 0.125 * q.k ------------------------
__global__ void qk_kernel()
{
    __shared__ float Ps[16][68];   // [d][n]
    __shared__ float Qs[16][68];   // [d][m]
    int m0 = blockIdx.x * 64, n0 = blockIdx.y * 64, z = blockIdx.z;
    int b = z >> 3, h = z & 7;
    int t = threadIdx.x;
    int tq = t & 15, tp = t >> 4;

    const float* Qb = g_q  + (size_t)b*Nn*Cc   + h*64;
    const float* Kb = g_kv + (size_t)b*Nn*2*Cc + h*64;

    float acc[4][4] = {};
    for (int d0 = 0; d0 < 64; d0 += 16) {
        int r  = t >> 2;
        int k4 = (t & 3) * 4;
        float4 qv = *(const float4*)&Qb[(size_t)(n0 + r)*Cc   + d0 + k4];
        float4 kv = *(const float4*)&Kb[(size_t)(m0 + r)*2*Cc + d0 + k4];
        Ps[k4+0][r] = qv.x; Ps[k4+1][r] = qv.y; Ps[k4+2][r] = qv.z; Ps[k4+3][r] = qv.w;
        Qs[k4+0][r] = kv.x; Qs[k4+1][r] = kv.y; Qs[k4+2][r] = kv.z; Qs[k4+3][r] = kv.w;
        __syncthreads();
        #pragma unroll
        for (int kk = 0; kk < 16; kk++) {
            float4 pv = *(const float4*)&Ps[kk][tp*4];
            float4 qv2 = *(const float4*)&Qs[kk][tq*4];
            float pa[4] = {pv.x, pv.y, pv.z, pv.w};
            float qa[4] = {qv2.x, qv2.y, qv2.z, qv2.w};
            #pragma unroll
            for (int i = 0; i < 4; i++)
                #pragma unroll
                for (int j = 0; j < 4; j++) acc[i][j] += pa[i]*qa[j];
        }
        __syncthreads();
    }
    float* A = g_attn + ((size_t)z*Nn + n0 + tp*4)*Nn + m0 + tq*4;
    #pragma unroll
    for (int i = 0; i < 4; i++) {
        float4 o = make_float4(acc[i][0]*0.125f, acc[i][1]*0.125f,
                               acc[i][2]*0.125f, acc[i][3]*0.125f);
        *(float4*)&A[(size_t)i*Nn] = o;
    }
}

// ---------------- kernel 6: exact top-k thresholds + fused dual softmax ------
__device__ __forceinline__ float key2f(unsigned k) {
    unsigned b = (k & 0x80000000u) ? (k ^ 0x80000000u) : ~k;
    return __uint_as_float(b);
}

__device__ __forceinline__ unsigned kth_key(const unsigned* key, int k)
{
    unsigned prefix = 0;
    int kk = k;
    for (int bit = 31; bit >= 0; --bit) {
        unsigned bm = 1u << bit;
        unsigned hi = (bit == 31) ? 0u : (0xFFFFFFFFu << (bit+1));
        int c = 0;
        #pragma unroll
        for (int i = 0; i < 32; i++) {
            unsigned v = key[i];
            c += (((v & hi) == prefix) && (v & bm)) ? 1 : 0;
        }
        c = __reduce_add_sync(0xffffffffu, c);
        if (c == kk) {
            unsigned mn = 0xFFFFFFFFu;
            #pragma unroll
            for (int i = 0; i < 32; i++) {
                unsigned v = key[i];
                if (((v & hi) == prefix) && (v & bm)) mn = min(mn, v);
            }
            return __reduce_min_sync(0xffffffffu, mn);
        } else if (c > kk) {
            prefix |= bm;
        } else {
            kk -= c;
        }
    }
    return prefix;
}

__global__ void select_kernel(const float* __restrict__ kr1, const float* __restrict__ kr2)
{
    int row  = blockIdx.x * 8 + (threadIdx.x >> 5);   // z*1024 + n
    int lane = threadIdx.x & 31;

    float r1 = kr1[0], r2 = kr2[0];
    int k1 = (int)(1024.f * (1.f/(1.f+expf(-r1)))); k1 = min(max(k1,1),1024);
    int k2 = (int)(1024.f * (1.f/(1.f+expf(-r2)))); k2 = min(max(k2,1),1024);

    float* rp = g_attn + (size_t)row * Nn;
    unsigned key[32];
    #pragma unroll
    for (int i = 0; i < 32; i++) {
        unsigned b = __float_as_uint(rp[i*32 + lane]);
        key[i] = (b & 0x80000000u) ? ~b : (b | 0x80000000u);
    }
    unsigned mx = 0;
    #pragma unroll
    for (int i = 0; i < 32; i++) mx = max(mx, key[i]);
    mx = __reduce_max_sync(0xffffffffu, mx);
    float M = key2f(mx);

    unsigned T1 = kth_key(key, k1);
    unsigned T2 = kth_key(key, k2);

    float s1 = 0.f, s2 = 0.f;
    #pragma unroll
    for (int i = 0; i < 32; i++) {
        float ev = __expf(key2f(key[i]) - M);
        if (key[i] >= T1) s1 += ev;
        if (key[i] >= T2) s2 += ev;
    }
    #pragma unroll
    for (int o = 16; o; o >>= 1) {
        s1 += __shfl_xor_sync(0xffffffffu, s1, o);
        s2 += __shfl_xor_sync(0xffffffffu, s2, o);
    }
    float c1 = 0.6f / s1, c2 = 0.4f / s2;
    #pragma unroll
    for (int i = 0; i < 32; i++) {
        float w = (key[i] >= T1 ? c1 : 0.f) + (key[i] >= T2 ? c2 : 0.f);
        rp[i*32 + lane] = __expf(key2f(key[i]) - M) * w;
    }
}

// ---------------- kernel 7: o[z,n,d] = coeff[z,n,:] @ v[z,:,d] ----------------
__global__ void av_kernel()
{
    __shared__ float As[16][68];   // [m][n]
    __shared__ float Bs[16][68];   // [m][d]
    int n0 = blockIdx.x * 64, z = blockIdx.y;
    int b = z >> 3, h = z & 7;
    int t = threadIdx.x;
    int tq = t & 15, tp = t >> 4;

    const float* Ab = g_attn + (size_t)z*Nn*Nn;
    const float* Vb = g_kv + (size_t)b*Nn*2*Cc + Cc + h*64;

    float acc[4][4] = {};
    for (int m0 = 0; m0 < Nn; m0 += 16) {
        {   // coeff tile transposed: As[m][n]
            int r  = t >> 2;
            int k4 = (t & 3) * 4;
            float4 v = *(const float4*)&Ab[(size_t)(n0 + r)*Nn + m0 + k4];
            As[k4+0][r] = v.x; As[k4+1][r] = v.y; As[k4+2][r] = v.z; As[k4+3][r] = v.w;
        }
        {   // v tile direct: Bs[m][d]
            int r  = t >> 4;
            int q4 = (t & 15) * 4;
            float4 v = *(const float4*)&Vb[(size_t)(m0 + r)*2*Cc + q4];
            *(float4*)&Bs[r][q4] = v;
        }
        __syncthreads();
        #pragma unroll
        for (int kk = 0; kk < 16; kk++) {
            float4 pv = *(const float4*)&As[kk][tp*4];
            float4 qv = *(const float4*)&Bs[kk][tq*4];
            float pa[4] = {pv.x, pv.y, pv.z, pv.w};
            float qa[4] = {qv.x, qv.y, qv.z, qv.w};
            #pragma unroll
            for (int i = 0; i < 4; i++)
                #pragma unroll
                for (int j = 0; j < 4; j++) acc[i][j] += pa[i]*qa[j];
        }
        __syncthreads();
    }
    float* O = g_o + ((size_t)b*Nn + n0 + tp*4)*Cc + h*64 + tq*4;
    #pragma unroll
    for (int i = 0; i < 4; i++) {
        float4 o = make_float4(acc[i][0], acc[i][1], acc[i][2], acc[i][3]);
        *(float4*)&O[(size_t)i*Cc] = o;
    }
}

// ------- kernel 8: out[b,c,n] = proj_w[c,:] . o[b,n,:] + b[c] + x[b,c,n] ------
__global__ void proj_kernel(const float* __restrict__ W, const float* __restrict__ bias,
                            const float* __restrict__ x, float* __restrict__ OUT)
{
    __shared__ float As[16][68];   // [k][n]
    __shared__ float Ws[16][68];   // [k][c]
    int c0 = blockIdx.x * 64, n0 = blockIdx.y * 64, b = blockIdx.z;
    int t = threadIdx.x;
    int tq = t & 15, tp = t >> 4;

    float acc[4][4] = {};
    for (int k0 = 0; k0 < Cc; k0 += 16) {
        int r  = t >> 2;
        int k4 = (t & 3) * 4;
        float4 a = *(const float4*)&g_o[(size_t)(b*Nn + n0 + r)*Cc + k0 + k4];
        As[k4+0][r] = a.x; As[k4+1][r] = a.y; As[k4+2][r] = a.z; As[k4+3][r] = a.w;
        float4 w = *(const float4*)&W[(size_t)(c0 + r)*Cc + k0 + k4];
        Ws[k4+0][r] = w.x; Ws[k4+1][r] = w.y; Ws[k4+2][r] = w.z; Ws[k4+3][r] = w.w;
        __syncthreads();
        #pragma unroll
        for (int kk = 0; kk < 16; kk++) {
            float4 wv = *(const float4*)&Ws[kk][tp*4];
            float4 av = *(const float4*)&As[kk][tq*4];
            float wa[4] = {wv.x, wv.y, wv.z, wv.w};
            float aa[4] = {av.x, av.y, av.z, av.w};
            #pragma unroll
            for (int i = 0; i < 4; i++)
                #pragma unroll
                for (int j = 0; j < 4; j++) acc[i][j] += wa[i]*aa[j];
        }
        __syncthreads();
    }
    #pragma unroll
    for (int i = 0; i < 4; i++) {
        int c = c0 + tp*4 + i;
        size_t idx = ((size_t)b*Cc + c)*Nn + n0 + tq*4;
        float4 res = *(const float4*)&x[idx];
        float bb = bias[c];
        float4 o = make_float4(acc[i][0] + bb + res.x, acc[i][1] + bb + res.y,
                               acc[i][2] + bb + res.z, acc[i][3] + bb + res.w);
        *(float4*)&OUT[idx] = o;
    }
}

// -----------------------------------------------------------------------------
extern "C" void kernel_launch(void* const* d_in, const int* in_sizes, int n_in,
                              void* d_out, int out_size)
{
    const float* x       = (const float*)d_in[0];
    const float* y       = (const float*)d_in[1];
    const float* q_w     = (const float*)d_in[2];
    const float* kv_w    = (const float*)d_in[3];
    const float* proj_w  = (const float*)d_in[4];
    const float* proj_b  = (const float*)d_in[5];
    const float* conv1_w = (const float*)d_in[6];
    const float* conv1_b = (const float*)d_in[7];
    const float* conv2_w = (const float*)d_in[8];
    const float* conv2_b = (const float*)d_in[9];
    const float* conv3_w = (const float*)d_in[10];
    const float* conv3_b = (const float*)d_in[11];
    const float* ln_w    = (const float*)d_in[12];
    const float* ln_b    = (const float*)d_in[13];
    const float* kr1     = (const float*)d_in[14];
    const float* kr2     = (const float*)d_in[15];
    float* out = (float*)d_out;

    float *yf_p, *yn_p, *q_p, *kv_p, *o_p;
    cudaGetSymbolAddress((void**)&yf_p, g_yf);
    cudaGetSymbolAddress((void**)&yn_p, g_yn);
    cudaGetSymbolAddress((void**)&q_p,  g_q);
    cudaGetSymbolAddress((void**)&kv_p, g_kv);
    cudaGetSymbolAddress((void**)&o_p,  g_o);

    conv_kernel<<<Bz*Cc, 256>>>(y, conv1_w, conv1_b, conv2_w, conv2_b, conv3_w, conv3_b);
    ln_kernel<<<Bz*32, 256>>>(ln_w, ln_b);
    gemm_xw_kernel<<<dim3(Cc/64, Nn/64, Bz), 256>>>(q_w, x, q_p, Cc);
    gemm_xw_kernel<<<dim3(2*Cc/64, Nn/64, Bz), 256>>>(kv_w, yn_p, kv_p, 2*Cc);
    qk_kernel<<<dim3(Nn/64, Nn/64, Bz*8), 256>>>();
    select_kernel<<<Bz*8*Nn/8, 256>>>(kr1, kr2);
    av_kernel<<<dim3(Nn/64, Bz*8), 256>>>();
    proj_kernel<<<dim3(Cc/64, Nn/64, Bz), 256>>>(proj_w, proj_b, x, out);
}

// round 3
// speedup vs baseline: 1.0481x; 1.0481x over previous
#include <cuda_runtime.h>
#include <cstdint>

#define Bz 8
#define Cc 512
#define Nn 1024

// ---------------- device scratch (no allocations allowed) --------------------
__device__ float g_yf[Bz*Cc*Nn];               // conv output [B,C,N]
__device__ float g_yn[Bz*Cc*Nn];               // layernorm output [B,C,N]
__device__ float g_q [Bz*Nn*Cc];               // q [B,N,C]
__device__ float g_kv[Bz*Nn*2*Cc];             // kv [B,N,2C] (k | v)
__device__ float g_o [Bz*Nn*Cc];               // attn out [B,N,C]
__device__ float g_attn[(size_t)64*1024*1024]; // attn/coeff [64 z][1024 n][1024 m]
__device__ float g_qwT [Cc*Cc];                // q_w^T    [ci][co]
__device__ float g_kvwT[Cc*2*Cc];              // kv_w^T   [ci][co]
__device__ float g_pwT [Cc*Cc];                // proj_w^T [ci][co]

// ---------------- kernel 0: 32x32 tiled transpose ----------------------------
__global__ void transpose_kernel(const float* __restrict__ A, float* __restrict__ At,
                                 int R, int C)
{
    __shared__ float tile[32][33];
    int c0 = blockIdx.x * 32, r0 = blockIdx.y * 32;
    int tx = threadIdx.x, ty = threadIdx.y;      // 32 x 8
    #pragma unroll
    for (int i = ty; i < 32; i += 8)
        tile[i][tx] = A[(size_t)(r0 + i) * C + c0 + tx];
    __syncthreads();
    #pragma unroll
    for (int i = ty; i < 32; i += 8)
        At[(size_t)(c0 + i) * R + r0 + tx] = tile[tx][i];
}

// ---------------- kernel 1: fused multi-scale depthwise conv -----------------
__global__ void conv_kernel(const float* __restrict__ y,
                            const float* __restrict__ w3, const float* __restrict__ b3,
                            const float* __restrict__ w5, const float* __restrict__ b5,
                            const float* __restrict__ w7, const float* __restrict__ b7)
{
    int bc = blockIdx.x;            // b*512 + c
    int c  = bc & (Cc-1);
    int t  = threadIdx.x;

    __shared__ float tile[38][38];
    __shared__ float wsum[49];
    __shared__ float bias;

    if (t < 49) {
        int dy = t / 7, dx = t % 7;
        float w = w7[c*49 + t];
        if (dy >= 1 && dy <= 5 && dx >= 1 && dx <= 5) w += w5[c*25 + (dy-1)*5 + (dx-1)];
        if (dy >= 2 && dy <= 4 && dx >= 2 && dx <= 4) w += w3[c*9  + (dy-2)*3 + (dx-2)];
        wsum[t] = w;
    }
    if (t == 64) bias = b3[c] + b5[c] + b7[c];

    const float* yp = y + (size_t)bc * Nn;
    for (int i = t; i < 38*38; i += 256) {
        int r  = i / 38 - 3;
        int cl = i % 38 - 3;
        float v = 0.f;
        if (r >= 0 && r < 32 && cl >= 0 && cl < 32) v = yp[r*32 + cl];
        tile[i/38][i%38] = v;
    }
    __syncthreads();

    float* op = g_yf + (size_t)bc * Nn;
    for (int i = t; i < 1024; i += 256) {
        int r = i >> 5, cl = i & 31;
        float acc = bias;
        #pragma unroll
        for (int dy = 0; dy < 7; dy++)
            #pragma unroll
            for (int dx = 0; dx < 7; dx++)
                acc += wsum[dy*7+dx] * tile[r+dy][cl+dx];
        op[i] = acc;
    }
}

// ---------------- kernel 2: layernorm over C per (b,n), layout [B,C,N] -------
__global__ void ln_kernel(const float* __restrict__ lnw, const float* __restrict__ lnb)
{
    int b    = blockIdx.x >> 5;
    int n0   = (blockIdx.x & 31) * 32;
    int lane = threadIdx.x & 31;
    int g    = threadIdx.x >> 5;            // 0..7
    int n    = n0 + lane;

    const float* base = g_yf + (size_t)b*Cc*Nn + n;
    float s = 0.f, s2 = 0.f;
    for (int c = g; c < Cc; c += 8) {
        float v = base[(size_t)c*Nn];
        s += v; s2 += v*v;
    }
    __shared__ float sh[2][8][32];
    sh[0][g][lane] = s; sh[1][g][lane] = s2;
    __syncthreads();
    if (g == 0) {
        float a = 0.f, a2 = 0.f;
        #pragma unroll
        for (int i = 0; i < 8; i++) { a += sh[0][i][lane]; a2 += sh[1][i][lane]; }
        float mu  = a * (1.f/512.f);
        float var = a2 * (1.f/512.f) - mu*mu;
        sh[0][0][lane] = mu;
        sh[1][0][lane] = rsqrtf(var + 1e-5f);
    }
    __syncthreads();
    float mu = sh[0][0][lane], rs = sh[1][0][lane];
    float* ob = g_yn + (size_t)b*Cc*Nn + n;
    for (int c = g; c < Cc; c += 8) {
        float v = base[(size_t)c*Nn];
        ob[(size_t)c*Nn] = (v - mu) * rs * lnw[c] + lnb[c];
    }
}

// ------- kernels 3/4: OUT[b,n,co] = sum_ci Xt[b,ci,n] * Wt[ci,co] -------------
// 128x128 tile, 256 threads, 8x8 microtile, both operands K-outer (no STS transpose)
__global__ void __launch_bounds__(256, 2)
gemm_nn_kernel(const float* __restrict__ Xt, const float* __restrict__ Wt,
               float* __restrict__ OUT, int CO)
{
    __shared__ float As[16][128];   // [ci][n]
    __shared__ float Bs[16][128];   // [ci][co]
    int co0 = blockIdx.x * 128, n0 = blockIdx.y * 128, b = blockIdx.z;
    int t = threadIdx.x, tx = t & 15, ty = t >> 4;
    const float* Xb = Xt + (size_t)b*Cc*Nn;

    int lr = t >> 4;            // 0..15
    int lc = (t & 15) * 8;      // 0..120

    float acc[8][8] = {};
    for (int k0 = 0; k0 < Cc; k0 += 16) {
        const float* xr = &Xb[(size_t)(k0 + lr)*Nn + n0 + lc];
        const float* wr = &Wt[(size_t)(k0 + lr)*CO + co0 + lc];
        float4 xa = *(const float4*)xr;       float4 xb = *(const float4*)(xr + 4);
        float4 wa = *(const float4*)wr;       float4 wb = *(const float4*)(wr + 4);
        *(float4*)&As[lr][lc] = xa;  *(float4*)&As[lr][lc+4] = xb;
        *(float4*)&Bs[lr][lc] = wa;  *(float4*)&Bs[lr][lc+4] = wb;
        __syncthreads();
        #pragma unroll
        for (int kk = 0; kk < 16; kk++) {
            float a[8], w[8];
            *(float4*)&a[0] = *(const float4*)&As[kk][ty*4];
            *(float4*)&a[4] = *(const float4*)&As[kk][64 + ty*4];
            *(float4*)&w[0] = *(const float4*)&Bs[kk][tx*4];
            *(float4*)&w[4] = *(const float4*)&Bs[kk][64 + tx*4];
            #pragma unroll
            for (int i = 0; i < 8; i++)
                #pragma unroll
                for (int j = 0; j < 8; j++) acc[i][j] += a[i]*w[j];
        }
        __syncthreads();
    }
    #pragma unroll
    for (int i = 0; i < 8; i++) {
        int n = n0 + (i < 4 ? ty*4 + i : 64 + ty*4 + (i-4));
        float* op = &OUT[((size_t)b*Nn + n)*CO + co0];
        *(float4*)&op[tx*4]      = make_float4(acc[i][0],acc[i][1],acc[i][2],acc[i][3]);
        *(float4*)&op[64 + tx*4] = make_float4(acc[i][4],acc[i][5],acc[i][6],acc[i][7]);
    }
}

// ---------------- kernel 5: attn[z,n,m] = 0.125 * q.k, 128x128 tiles ---------
__global__ void __launch_bounds__(256, 2) qk_kernel()
{
    __shared__ float Qs[16][132];   // [d][n]
    __shared__ float Ks[16][132];   // [d][m]
    int m0 = blockIdx.x * 128, n0 = blockIdx.y * 128, z = blockIdx.z;
    int b = z >> 3, h = z & 7;
    int t = threadIdx.x, tx = t & 15, ty = t >> 4;

    const float* Qb = g_q  + (size_t)b*Nn*Cc   + h*64;
    const float* Kb = g_kv + (size_t)b*Nn*2*Cc + h*64;

    int lr = t >> 1;            // 0..127
    int lk = (t & 1) * 8;       // 0 or 8

    float acc[8][8] = {};
    for (int d0 = 0; d0 < 64; d0 += 16) {
        const float* qr = &Qb[(size_t)(n0 + lr)*Cc   + d0 + lk];
        const float* kr = &Kb[(size_t)(m0 + lr)*2*Cc + d0 + lk];
        float4 q0 = *(const float4*)qr; float4 q1 = *(const float4*)(qr + 4);
        float4 k0 = *(const float4*)kr; float4 k1 = *(const float4*)(kr + 4);
        Qs[lk+0][lr]=q0.x; Qs[lk+1][lr]=q0.y; Qs[lk+2][lr]=q0.z; Qs[lk+3][lr]=q0.w;
        Qs[lk+4][lr]=q1.x; Qs[lk+5][lr]=q1.y; Qs[lk+6][lr]=q1.z; Qs[lk+7][lr]=q1.w;
        Ks[lk+0][lr]=k0.x; Ks[lk+1][lr]=k0.y; Ks[lk+2][lr]=k0.z; Ks[lk+3][lr]=k0.w;
        Ks[lk+4][lr]=k1.x; Ks[lk+5][lr]=k1.y; Ks[lk+6][lr]=k1.z; Ks[lk+7][lr]=k1.w;
        __syncthreads();
        #pragma unroll
        for (int kk = 0; kk < 16; kk++) {
            float a[8], w[8];
            *(float4*)&a[0] = *(const float4*)&Qs[kk][ty*4];
            *(float4*)&a[4] = *(const float4*)&Qs[kk][64 + ty*4];
            *(float4*)&w[0] = *(const float4*)&Ks[kk][tx*4];
            *(float4*)&w[4] = *(const float4*)&Ks[kk][64 + tx*4];
            #pragma unroll
            for (int i = 0; i < 8; i++)
                #pragma unroll
                for (int j = 0; j < 8; j++) acc[i][j] += a[i]*w[j];
        }
        __syncthreads();
    }
    #pragma unroll
    for (int i = 0; i < 8; i++) {
        int n = n0 + (i < 4 ? ty*4 + i : 64 + ty*4 + (i-4));
        float* A = g_attn + ((size_t)z*Nn + n)*Nn + m0;
        *(float4*)&A[tx*4]      = make_float4(acc[i][0]*0.125f, acc[i][1]*0.125f,
                                              acc[i][2]*0.125f, acc[i][3]*0.125f);
        *(float4*)&A[64 + tx*4] = make_float4(acc[i][4]*0.125f, acc[i][5]*0.125f,
                                              acc[i][6]*0.125f, acc[i][7]*0.125f);
    }
}

// ---------------- kernel 6: exact top-k thresholds + fused dual softmax ------
__device__ __forceinline__ float key2f(unsigned k) {
    unsigned b = (k & 0x80000000u) ? (k ^ 0x80000000u) : ~k;
    return __uint_as_float(b);
}

__device__ __forceinline__ unsigned kth_key(const unsigned* key, int k)
{
    unsigned prefix = 0;
    int kk = k;
    for (int bit = 31; bit >= 0; --bit) {
        unsigned bm = 1u << bit;
        unsigned hi = (bit == 31) ? 0u : (0xFFFFFFFFu << (bit+1));
        int c = 0;
        #pragma unroll
        for (int i = 0; i < 32; i++) {
            unsigned v = key[i];
            c += (((v & hi) == prefix) && (v & bm)) ? 1 : 0;
        }
        c = __reduce_add_sync(0xffffffffu, c);
        if (c == kk) {
            unsigned mn = 0xFFFFFFFFu;
            #pragma unroll
            for (int i = 0; i < 32; i++) {
                unsigned v = key[i];
                if (((v & hi) == prefix) && (v & bm)) mn = min(mn, v);
            }
            return __reduce_min_sync(0xffffffffu, mn);
        } else if (c > kk) {
            prefix |= bm;
        } else {
            kk -= c;
        }
    }
    return prefix;
}

__global__ void select_kernel(const float* __restrict__ kr1, const float* __restrict__ kr2)
{
    int row  = blockIdx.x * 8 + (threadIdx.x >> 5);   // z*1024 + n
    int lane = threadIdx.x & 31;

    float r1 = kr1[0], r2 = kr2[0];
    int k1 = (int)(1024.f * (1.f/(1.f+expf(-r1)))); k1 = min(max(k1,1),1024);
    int k2 = (int)(1024.f * (1.f/(1.f+expf(-r2)))); k2 = min(max(k2,1),1024);

    float* rp = g_attn + (size_t)row * Nn;
    unsigned key[32];
    #pragma unroll
    for (int i = 0; i < 32; i++) {
        unsigned b = __float_as_uint(rp[i*32 + lane]);
        key[i] = (b & 0x80000000u) ? ~b : (b | 0x80000000u);
    }
    unsigned mx = 0;
    #pragma unroll
    for (int i = 0; i < 32; i++) mx = max(mx, key[i]);
    mx = __reduce_max_sync(0xffffffffu, mx);
    float M = key2f(mx);

    unsigned T1 = kth_key(key, k1);
    unsigned T2 = kth_key(key, k2);

    float s1 = 0.f, s2 = 0.f;
    #pragma unroll
    for (int i = 0; i < 32; i++) {
        float ev = __expf(key2f(key[i]) - M);
        if (key[i] >= T1) s1 += ev;
        if (key[i] >= T2) s2 += ev;
    }
    #pragma unroll
    for (int o = 16; o; o >>= 1) {
        s1 += __shfl_xor_sync(0xffffffffu, s1, o);
        s2 += __shfl_xor_sync(0xffffffffu, s2, o);
    }
    float c1 = 0.6f / s1, c2 = 0.4f / s2;
    #pragma unroll
    for (int i = 0; i < 32; i++) {
        float w = (key[i] >= T1 ? c1 : 0.f) + (key[i] >= T2 ? c2 : 0.f);
        rp[i*32 + lane] = __expf(key2f(key[i]) - M) * w;
    }
}

// ---------------- kernel 7: o[z,n,d] = coeff[z,n,:] @ v[z,:,d] ----------------
// 128n x 64d tile, 256 threads (16d x 16n), 8x4 microtile
__global__ void __launch_bounds__(256, 2) av_kernel()
{
    __shared__ float As[16][132];   // [m][n]
    __shared__ float Bs[16][68];    // [m][d]
    int n0 = blockIdx.x * 128, z = blockIdx.y;
    int b = z >> 3, h = z & 7;
    int t = threadIdx.x, tx = t & 15, ty = t >> 4;

    const float* Ab = g_attn + (size_t)z*Nn*Nn;
    const float* Vb = g_kv + (size_t)b*Nn*2*Cc + Cc + h*64;

    int lr = t >> 1;            // 0..127 (coeff row within tile)
    int lk = (t & 1) * 8;       // m offset
    int vr = t >> 4;            // 0..15  (v row)
    int vc = (t & 15) * 4;      // v col

    float acc[8][4] = {};
    for (int m0 = 0; m0 < Nn; m0 += 16) {
        const float* ar = &Ab[(size_t)(n0 + lr)*Nn + m0 + lk];
        float4 a0 = *(const float4*)ar; float4 a1 = *(const float4*)(ar + 4);
        As[lk+0][lr]=a0.x; As[lk+1][lr]=a0.y; As[lk+2][lr]=a0.z; As[lk+3][lr]=a0.w;
        As[lk+4][lr]=a1.x; As[lk+5][lr]=a1.y; As[lk+6][lr]=a1.z; As[lk+7][lr]=a1.w;
        float4 vv = *(const float4*)&Vb[(size_t)(m0 + vr)*2*Cc + vc];
        *(float4*)&Bs[vr][vc] = vv;
        __syncthreads();
        #pragma unroll
        for (int kk = 0; kk < 16; kk++) {
            float a[8], w[4];
            *(float4*)&a[0] = *(const float4*)&As[kk][ty*4];
            *(float4*)&a[4] = *(const float4*)&As[kk][64 + ty*4];
            *(float4*)&w[0] = *(const float4*)&Bs[kk][tx*4];
            #pragma unroll
            for (int i = 0; i < 8; i++)
                #pragma unroll
                for (int j = 0; j < 4; j++) acc[i][j] += a[i]*w[j];
        }
        __syncthreads();
    }
    #pragma unroll
    for (int i = 0; i < 8; i++) {
        int n = n0 + (i < 4 ? ty*4 + i : 64 + ty*4 + (i-4));
        *(float4*)&g_o[((size_t)b*Nn + n)*Cc + h*64 + tx*4] =
            make_float4(acc[i][0], acc[i][1], acc[i][2], acc[i][3]);
    }
}

// ------- kernel 8: out[b,c,n] = proj_w[c,:].o[b,n,:] + b[c] + x[b,c,n] --------
__global__ void __launch_bounds__(256, 2)
proj_kernel(const float* __restrict__ Wt, const float* __restrict__ bias,
            const float* __restrict__ x, float* __restrict__ OUT)
{
    __shared__ float As[16][132];   // [k][n]  (from g_o, transposed)
    __shared__ float Bs[16][128];   // [k][c]  (from Wt, direct)
    int c0 = blockIdx.x * 128, n0 = blockIdx.y * 128, b = blockIdx.z;
    int t = threadIdx.x, tx = t & 15, ty = t >> 4;

    int lr = t >> 1;            // 0..127
    int lk = (t & 1) * 8;
    int wr = t >> 4;            // 0..15
    int wc = (t & 15) * 8;

    float acc[8][8] = {};
    for (int k0 = 0; k0 < Cc; k0 += 16) {
        const float* ar = &g_o[((size_t)b*Nn + n0 + lr)*Cc + k0 + lk];
        float4 a0 = *(const float4*)ar; float4 a1 = *(const float4*)(ar + 4);
        As[lk+0][lr]=a0.x; As[lk+1][lr]=a0.y; As[lk+2][lr]=a0.z; As[lk+3][lr]=a0.w;
        As[lk+4][lr]=a1.x; As[lk+5][lr]=a1.y; As[lk+6][lr]=a1.z; As[lk+7][lr]=a1.w;
        const float* wrp = &Wt[(size_t)(k0 + wr)*Cc + c0 + wc];
        *(float4*)&Bs[wr][wc]   = *(const float4*)wrp;
        *(float4*)&Bs[wr][wc+4] = *(const float4*)(wrp + 4);
        __syncthreads();
        #pragma unroll
        for (int kk = 0; kk < 16; kk++) {
            float a[8], w[8];
            *(float4*)&a[0] = *(const float4*)&As[kk][ty*4];
            *(float4*)&a[4] = *(const float4*)&As[kk][64 + ty*4];
            *(float4*)&w[0] = *(const float4*)&Bs[kk][tx*4];
            *(float4*)&w[4] = *(const float4*)&Bs[kk][64 + tx*4];
            #pragma unroll
            for (int i = 0; i < 8; i++)
                #pragma unroll
                for (int j = 0; j < 8; j++) acc[i][j] += a[i]*w[j];
        }
        __syncthreads();
    }
    // acc[i][j]: i -> n rows, j -> c cols. Store transposed to OUT[b,c,n] + bias + x.
    #pragma unroll
    for (int j = 0; j < 8; j++) {
        int c = c0 + (j < 4 ? tx*4 + j : 64 + tx*4 + (j-4));
        float bb = bias[c];
        size_t base = ((size_t)b*Cc + c)*Nn;
        int na = n0 + ty*4;
        float4 r0 = *(const float4*)&x[base + na];
        *(float4*)&OUT[base + na] = make_float4(acc[0][j]+bb+r0.x, acc[1][j]+bb+r0.y,
                                                acc[2][j]+bb+r0.z, acc[3][j]+bb+r0.w);
        int nb = n0 + 64 + ty*4;
        float4 r1 = *(const float4*)&x[base + nb];
        *(float4*)&OUT[base + nb] = make_float4(acc[4][j]+bb+r1.x, acc[5][j]+bb+r1.y,
                                                acc[6][j]+bb+r1.z, acc[7][j]+bb+r1.w);
    }
}

// -----------------------------------------------------------------------------
extern "C" void kernel_launch(void* const* d_in, const int* in_sizes, int n_in,
                              void* d_out, int out_size)
{
    const float* x       = (const float*)d_in[0];
    const float* y       = (const float*)d_in[1];
    const float* q_w     = (const float*)d_in[2];
    const float* kv_w    = (const float*)d_in[3];
    const float* proj_w  = (const float*)d_in[4];
    const float* proj_b  = (const float*)d_in[5];
    const float* conv1_w = (const float*)d_in[6];
    const float* conv1_b = (const float*)d_in[7];
    const float* conv2_w = (const float*)d_in[8];
    const float* conv2_b = (const float*)d_in[9];
    const float* conv3_w = (const float*)d_in[10];
    const float* conv3_b = (const float*)d_in[11];
    const float* ln_w    = (const float*)d_in[12];
    const float* ln_b    = (const float*)d_in[13];
    const float* kr1     = (const float*)d_in[14];
    const float* kr2     = (const float*)d_in[15];
    float* out = (float*)d_out;

    float *yn_p, *q_p, *kv_p, *qwT, *kvwT, *pwT;
    cudaGetSymbolAddress((void**)&yn_p, g_yn);
    cudaGetSymbolAddress((void**)&q_p,  g_q);
    cudaGetSymbolAddress((void**)&kv_p, g_kv);
    cudaGetSymbolAddress((void**)&qwT,  g_qwT);
    cudaGetSymbolAddress((void**)&kvwT, g_kvwT);
    cudaGetSymbolAddress((void**)&pwT,  g_pwT);

    dim3 tb(32, 8);
    transpose_kernel<<<dim3(16, 16), tb>>>(q_w,    qwT,  Cc,   Cc);
    transpose_kernel<<<dim3(16, 32), tb>>>(kv_w,   kvwT, 2*Cc, Cc);
    transpose_kernel<<<dim3(16, 16), tb>>>(proj_w, pwT,  Cc,   Cc);

    conv_kernel<<<Bz*Cc, 256>>>(y, conv1_w, conv1_b, conv2_w, conv2_b, conv3_w, conv3_b);
    ln_kernel<<<Bz*32, 256>>>(ln_w, ln_b);

    gemm_nn_kernel<<<dim3(Cc/128,   Nn/128, Bz), 256>>>(x,    qwT,  q_p,  Cc);
    gemm_nn_kernel<<<dim3(2*Cc/128, Nn/128, Bz), 256>>>(yn_p, kvwT, kv_p, 2*Cc);

    qk_kernel<<<dim3(Nn/128, Nn/128, Bz*8), 256>>>();
    select_kernel<<<Bz*8*Nn/8, 256>>>(kr1, kr2);
    av_kernel<<<dim3(Nn/128, Bz*8), 256>>>();
    proj_kernel<<<dim3(Cc/128, Nn/128, Bz), 256>>>(pwT, proj_b, x, out);
}